// round 6
// baseline (speedup 1.0000x reference)
#include <cuda_runtime.h>
#include <math.h>

// ---- static problem dims ----
#define BN      64      // batch (nodes)
#define NCL     128
#define NC      512     // total channels
#define REP     2048    // rep components
#define DD      512     // folded dim
#define NORM_EPS 1e-2f
#define BN_EPS   1e-5f

__device__ __constant__ int REP_OFF_C[4] = {0, 128, 512, 1152};

// ---- scratch (__device__ globals: allocation-free) ----
__device__ float g_s[BN * REP];      // gauge tensor
__device__ float norm_s[BN * NC];    // per-(l,channel) norms
__device__ float nbn_s[BN * NC];     // batchnormed norms
__device__ float h_s[BN * NC];       // MLP hidden
__device__ float n1_s[BN * NC];      // MLP out
__device__ float partN_s[BN][64][4]; // per-node per-chunk bilinear partials
__device__ int   barN_s[BN];         // per-node arrival counters

// ============================================================
// K0: zero the per-node counters (fresh every graph replay).
// ============================================================
__global__ void k_init() {
    if (threadIdx.x < BN) barN_s[threadIdx.x] = 0;
}

// ============================================================
// K1: per-node norms + gauge tensor.  One block per n.
// ============================================================
__global__ void k_norm_gauge(const float* __restrict__ x1d) {
    int n = blockIdx.x;
    __shared__ float xs[REP];   // 8 KB
    __shared__ float ns[NC];    // 2 KB
    const float* xr = x1d + n * REP;
    for (int i = threadIdx.x; i < REP; i += 256) xs[i] = xr[i];
    __syncthreads();
    for (int c = threadIdx.x; c < NC; c += 256) {
        int l = c >> 7, j = c & 127, off = REP_OFF_C[l], nm = 2 * l + 1;
        float s = 0.f;
        #pragma unroll 7
        for (int m = 0; m < nm; m++) { float v = xs[off + m * 128 + j]; s += v * v; }
        float nv = sqrtf(s);
        ns[c] = nv;
        norm_s[n * NC + c] = nv;
    }
    __syncthreads();
    for (int r = threadIdx.x; r < REP; r += 256) {
        int l = (r < 128) ? 0 : (r < 512) ? 1 : (r < 1152) ? 2 : 3;
        int c = l * 128 + ((r - REP_OFF_C[l]) & 127);
        g_s[n * REP + r] = xs[r] / (ns[c] + NORM_EPS);
    }
}

// ============================================================
// K2: batchnorm over batch axis. grid 4 x 128 threads.
// ============================================================
__global__ void k_bn() {
    int c = blockIdx.x * 128 + threadIdx.x;
    float mu = 0.f;
    #pragma unroll 8
    for (int n = 0; n < BN; n++) mu += norm_s[n * NC + c];
    mu *= (1.f / BN);
    float var = 0.f;
    #pragma unroll 8
    for (int n = 0; n < BN; n++) { float d = norm_s[n * NC + c] - mu; var += d * d; }
    var *= (1.f / BN);
    float inv = 1.f / sqrtf(var + BN_EPS);
    #pragma unroll 8
    for (int n = 0; n < BN; n++) nbn_s[n * NC + c] = (norm_s[n * NC + c] - mu) * inv;
}

// ============================================================
// K3/K4: [64,512] @ W^T + bias, optional swish.
// Warp-per-output-channel; W loaded via 4 LDG.128 (wide, batched);
// X staged transposed xs[k][12] so 8 n-values come from 2 LDS.128.
// ============================================================
__global__ void k_gemm(const float* __restrict__ W, const float* __restrict__ bias, int which) {
    const float* X = which ? h_s : nbn_s;
    float* Y       = which ? n1_s : h_s;
    __shared__ float xs[512][12];   // 24 KB, transposed
    int ng  = blockIdx.y * 8;
    int tid = threadIdx.x, warp = tid >> 5, lane = tid & 31;
    int o = blockIdx.x * 8 + warp;
    for (int i = tid; i < 8 * 512; i += 256) {
        int j = i >> 9, k = i & 511;
        xs[k][j] = X[(ng + j) * NC + k];
    }
    __syncthreads();
    const float4* wrow4 = (const float4*)(W + o * NC);
    float a0=0.f,a1=0.f,a2=0.f,a3=0.f,a4=0.f,a5=0.f,a6=0.f,a7=0.f;
    #pragma unroll
    for (int j = 0; j < 4; j++) {
        int kq = lane + (j << 5);          // float4 index: k = 4*kq..4*kq+3
        float4 w4 = wrow4[kq];
        float wv[4] = {w4.x, w4.y, w4.z, w4.w};
        #pragma unroll
        for (int t = 0; t < 4; t++) {
            int k = kq * 4 + t;
            float w = wv[t];
            float4 xa = *(const float4*)&xs[k][0];
            float4 xb = *(const float4*)&xs[k][4];
            a0 = fmaf(w, xa.x, a0);
            a1 = fmaf(w, xa.y, a1);
            a2 = fmaf(w, xa.z, a2);
            a3 = fmaf(w, xa.w, a3);
            a4 = fmaf(w, xb.x, a4);
            a5 = fmaf(w, xb.y, a5);
            a6 = fmaf(w, xb.z, a6);
            a7 = fmaf(w, xb.w, a7);
        }
    }
    #pragma unroll
    for (int s = 16; s > 0; s >>= 1) {
        a0 += __shfl_xor_sync(0xffffffff, a0, s);
        a1 += __shfl_xor_sync(0xffffffff, a1, s);
        a2 += __shfl_xor_sync(0xffffffff, a2, s);
        a3 += __shfl_xor_sync(0xffffffff, a3, s);
        a4 += __shfl_xor_sync(0xffffffff, a4, s);
        a5 += __shfl_xor_sync(0xffffffff, a5, s);
        a6 += __shfl_xor_sync(0xffffffff, a6, s);
        a7 += __shfl_xor_sync(0xffffffff, a7, s);
    }
    if (lane == 0) {
        float b = bias[o];
        float v[8] = {a0+b, a1+b, a2+b, a3+b, a4+b, a5+b, a6+b, a7+b};
        #pragma unroll
        for (int j = 0; j < 8; j++) {
            float u = v[j];
            if (!which) u = u / (1.f + expf(-u));   // swish
            Y[(ng + j) * NC + o] = u;
        }
    }
}

// ============================================================
// K5: IELin fused with scalar_mul -> x1d_new (into d_out).
// ============================================================
__global__ void k_ielin(const float* __restrict__ Wie, float* __restrict__ x1dout) {
    __shared__ float gsT[128][12];  // 6 KB, transposed
    __shared__ int nrow[8], mrow[8];
    int rowbase = blockIdx.x * 8;
    int l, lbase;
    if (rowbase < 64)       { l = 0; lbase = 0; }
    else if (rowbase < 256) { l = 1; lbase = 64; }
    else if (rowbase < 576) { l = 2; lbase = 256; }
    else                    { l = 3; lbase = 576; }
    int nm = 2 * l + 1, off = REP_OFF_C[l];
    int tid = threadIdx.x, warp = tid >> 5, lane = tid & 31;
    if (tid < 8) {
        int rr = rowbase + tid - lbase;
        nrow[tid] = rr / nm;
        mrow[tid] = rr - nrow[tid] * nm;
    }
    __syncthreads();
    for (int idx = tid; idx < 8 * 128; idx += 256) {
        int j = idx >> 7, i = idx & 127;
        gsT[i][j] = g_s[nrow[j] * REP + off + mrow[j] * 128 + i];
    }
    __syncthreads();
    int o = blockIdx.y * 8 + warp;
    const float4* wrow4 = (const float4*)(Wie + (l * 128 + o) * 128);
    float a0=0.f,a1=0.f,a2=0.f,a3=0.f,a4=0.f,a5=0.f,a6=0.f,a7=0.f;
    {
        float4 w4 = wrow4[lane];
        float wv[4] = {w4.x, w4.y, w4.z, w4.w};
        #pragma unroll
        for (int t = 0; t < 4; t++) {
            int k = lane * 4 + t;
            float w = wv[t];
            float4 ga = *(const float4*)&gsT[k][0];
            float4 gb = *(const float4*)&gsT[k][4];
            a0 = fmaf(w, ga.x, a0);
            a1 = fmaf(w, ga.y, a1);
            a2 = fmaf(w, ga.z, a2);
            a3 = fmaf(w, ga.w, a3);
            a4 = fmaf(w, gb.x, a4);
            a5 = fmaf(w, gb.y, a5);
            a6 = fmaf(w, gb.z, a6);
            a7 = fmaf(w, gb.w, a7);
        }
    }
    #pragma unroll
    for (int s = 16; s > 0; s >>= 1) {
        a0 += __shfl_xor_sync(0xffffffff, a0, s);
        a1 += __shfl_xor_sync(0xffffffff, a1, s);
        a2 += __shfl_xor_sync(0xffffffff, a2, s);
        a3 += __shfl_xor_sync(0xffffffff, a3, s);
        a4 += __shfl_xor_sync(0xffffffff, a4, s);
        a5 += __shfl_xor_sync(0xffffffff, a5, s);
        a6 += __shfl_xor_sync(0xffffffff, a6, s);
        a7 += __shfl_xor_sync(0xffffffff, a7, s);
    }
    if (lane == 0) {
        float acc[8] = {a0, a1, a2, a3, a4, a5, a6, a7};
        #pragma unroll
        for (int j = 0; j < 8; j++) {
            int n = nrow[j];
            x1dout[n * REP + off + mrow[j] * 128 + o] =
                acc[j] * n1_s[n * NC + l * 128 + o];
        }
    }
}

// ============================================================
// K6 (fused, node-staggered): reduce + gate + gated apply.
// 512 blocks; block b = (nin = b>>6, chunk = b&63) serves nodes
// n = g*8+nin for g=0..7 IN SEQUENCE.  Only ~8 nodes (32 MB) are in
// flight at any time, so each block's phase-B re-read of its own
// 64 KB happens within a <64 MB traffic window -> L2 hits.
// Per-node barrier: 64 participants, volatile-poll (no RMW storm).
// Nodes never wait on each other -> DRAM stays busy (no R4 stalls).
// ============================================================
__global__ void __launch_bounds__(256, 4)
k_two(const float* __restrict__ x2d, const float* __restrict__ x1dnew,
      const float* __restrict__ Wg, const float* __restrict__ bg,
      const float* __restrict__ Wt, float* __restrict__ x2dout) {
    int nin = blockIdx.x >> 6, chunk = blockIdx.x & 63;
    int tid = threadIdx.x, warp = tid >> 5, lane = tid & 31;
    __shared__ float4 fs[512];      // 8 KB
    __shared__ float wacc[8][4];
    __shared__ float red[2][4];
    __shared__ float Msh[16];

    for (int g = 0; g < 8; g++) {
        int n = g * 8 + nin;
        __syncthreads();   // fs reuse guard
        const float4* f4 = (const float4*)x1dnew + n * 512;
        for (int q = tid; q < 512; q += 256) fs[q] = f4[q];
        __syncthreads();

        // ---- phase A: this block reduces 8 rows (1 per warp) ----
        int p = chunk * 8 + warp;
        const float4* row = (const float4*)x2d + ((size_t)n * 512 + p) * 512;
        float4 fp = fs[p];
        float ax = 0.f, ay = 0.f, az = 0.f, aw = 0.f;
        #pragma unroll
        for (int j = 0; j < 16; j++) {
            int q = lane + (j << 5);
            float4 v  = row[q];
            float4 fq = fs[q];
            ax = fmaf(v.x * fq.x, fp.x, ax);
            ay = fmaf(v.y * fq.y, fp.y, ay);
            az = fmaf(v.z * fq.z, fp.z, az);
            aw = fmaf(v.w * fq.w, fp.w, aw);
        }
        #pragma unroll
        for (int s = 16; s > 0; s >>= 1) {
            ax += __shfl_xor_sync(0xffffffff, ax, s);
            ay += __shfl_xor_sync(0xffffffff, ay, s);
            az += __shfl_xor_sync(0xffffffff, az, s);
            aw += __shfl_xor_sync(0xffffffff, aw, s);
        }
        if (lane == 0) { wacc[warp][0] = ax; wacc[warp][1] = ay; wacc[warp][2] = az; wacc[warp][3] = aw; }
        __syncthreads();
        if (tid < 4) {
            float s = 0.f;
            #pragma unroll
            for (int w = 0; w < 8; w++) s += wacc[w][tid];
            partN_s[n][chunk][tid] = s;
            __threadfence();
        }
        __syncthreads();

        // ---- per-node barrier: 64 participants, volatile polling ----
        if (tid == 0) {
            atomicAdd(&barN_s[n], 1);
            while (*(volatile int*)&barN_s[n] < 64) __nanosleep(128);
        }
        __syncthreads();
        __threadfence();

        // ---- gate (redundant per block, deterministic shfl tree) ----
        if (tid < 64) {
            volatile float* pp = &partN_s[n][tid][0];
            float c0 = pp[0], c1 = pp[1], c2 = pp[2], c3 = pp[3];
            #pragma unroll
            for (int s = 16; s > 0; s >>= 1) {
                c0 += __shfl_xor_sync(0xffffffff, c0, s);
                c1 += __shfl_xor_sync(0xffffffff, c1, s);
                c2 += __shfl_xor_sync(0xffffffff, c2, s);
                c3 += __shfl_xor_sync(0xffffffff, c3, s);
            }
            if (lane == 0) { red[warp][0] = c0; red[warp][1] = c1; red[warp][2] = c2; red[warp][3] = c3; }
        }
        __syncthreads();
        if (tid == 0) {
            float a2[4];
            #pragma unroll
            for (int c = 0; c < 4; c++) a2[c] = red[0][c] + red[1][c];
            #pragma unroll
            for (int d = 0; d < 4; d++) {
                float pre = bg[d];
                #pragma unroll
                for (int c = 0; c < 4; c++) pre = fmaf(a2[c], Wg[d * 4 + c], pre);
                float gate = pre / (1.f + expf(-pre));
                #pragma unroll
                for (int c = 0; c < 4; c++) Msh[d * 4 + c] = gate * Wt[d * 4 + c];
            }
        }
        __syncthreads();

        // ---- phase B: gated 4x4 matvec over same rows (L2-hot) ----
        float m[16];
        #pragma unroll
        for (int i = 0; i < 16; i++) m[i] = Msh[i];
        float4* orow = (float4*)x2dout + ((size_t)n * 512 + p) * 512;
        #pragma unroll
        for (int j = 0; j < 16; j++) {
            int q = lane + (j << 5);
            float4 v = row[q];
            float4 o;
            o.x = m[0]  * v.x + m[1]  * v.y + m[2]  * v.z + m[3]  * v.w;
            o.y = m[4]  * v.x + m[5]  * v.y + m[6]  * v.z + m[7]  * v.w;
            o.z = m[8]  * v.x + m[9]  * v.y + m[10] * v.z + m[11] * v.w;
            o.w = m[12] * v.x + m[13] * v.y + m[14] * v.z + m[15] * v.w;
            orow[q] = o;
        }
    }
}

// ============================================================
extern "C" void kernel_launch(void* const* d_in, const int* in_sizes, int n_in,
                              void* d_out, int out_size) {
    const float* x1d = (const float*)d_in[0];
    const float* x2d = (const float*)d_in[1];
    const float* W1  = (const float*)d_in[2];
    const float* b1  = (const float*)d_in[3];
    const float* W2  = (const float*)d_in[4];
    const float* b2  = (const float*)d_in[5];
    const float* Wie = (const float*)d_in[6];
    const float* Wt  = (const float*)d_in[7];
    const float* Wg  = (const float*)d_in[8];
    const float* bg  = (const float*)d_in[9];
    float* out = (float*)d_out;
    float* x1dnew = out;                       // [64, 2048]
    float* x2dnew = out + (size_t)BN * REP;    // [64, 512, 512, 4]

    k_init<<<1, 64>>>();
    k_norm_gauge<<<BN, 256>>>(x1d);
    k_bn<<<4, 128>>>();
    k_gemm<<<dim3(64, 8), 256>>>(W1, b1, 0);   // swish
    k_gemm<<<dim3(64, 8), 256>>>(W2, b2, 1);   // linear
    k_ielin<<<dim3(128, 16), 256>>>(Wie, x1dnew);
    k_two<<<512, 256>>>(x2d, x1dnew, Wg, bg, Wt, x2dnew);
}

// round 8
// speedup vs baseline: 1.1825x; 1.1825x over previous
#include <cuda_runtime.h>
#include <math.h>

// ---- static problem dims ----
#define BN      64      // batch (nodes)
#define NCL     128
#define NC      512     // total channels
#define REP     2048    // rep components
#define DD      512     // folded dim
#define NORM_EPS 1e-2f
#define BN_EPS   1e-5f

__device__ __constant__ int REP_OFF_C[4] = {0, 128, 512, 1152};

// ---- scratch (__device__ globals: allocation-free) ----
__device__ float g_s[BN * REP];      // gauge tensor
__device__ float norm_s[BN * NC];    // per-(l,channel) norms
__device__ float nbn_s[BN * NC];     // batchnormed norms
__device__ float h_s[BN * NC];       // MLP hidden
__device__ float n1_s[BN * NC];      // MLP out
__device__ float partN_s[BN][8][4];  // per-node per-segment bilinear partials
__device__ int   barN_s[BN];         // per-node arrival counters

// ============================================================
// K0: zero the per-node counters (fresh every graph replay).
// ============================================================
__global__ void k_init() {
    if (threadIdx.x < BN) barN_s[threadIdx.x] = 0;
}

// ============================================================
// K1: per-node norms + gauge tensor.  One block per n.
// ============================================================
__global__ void k_norm_gauge(const float* __restrict__ x1d) {
    int n = blockIdx.x;
    __shared__ float xs[REP];   // 8 KB
    __shared__ float ns[NC];    // 2 KB
    const float* xr = x1d + n * REP;
    for (int i = threadIdx.x; i < REP; i += 256) xs[i] = xr[i];
    __syncthreads();
    for (int c = threadIdx.x; c < NC; c += 256) {
        int l = c >> 7, j = c & 127, off = REP_OFF_C[l], nm = 2 * l + 1;
        float s = 0.f;
        #pragma unroll 7
        for (int m = 0; m < nm; m++) { float v = xs[off + m * 128 + j]; s += v * v; }
        float nv = sqrtf(s);
        ns[c] = nv;
        norm_s[n * NC + c] = nv;
    }
    __syncthreads();
    for (int r = threadIdx.x; r < REP; r += 256) {
        int l = (r < 128) ? 0 : (r < 512) ? 1 : (r < 1152) ? 2 : 3;
        int c = l * 128 + ((r - REP_OFF_C[l]) & 127);
        g_s[n * REP + r] = xs[r] / (ns[c] + NORM_EPS);
    }
}

// ============================================================
// K2: batchnorm over batch axis. grid 4 x 128 threads.
// ============================================================
__global__ void k_bn() {
    int c = blockIdx.x * 128 + threadIdx.x;
    float mu = 0.f;
    #pragma unroll 8
    for (int n = 0; n < BN; n++) mu += norm_s[n * NC + c];
    mu *= (1.f / BN);
    float var = 0.f;
    #pragma unroll 8
    for (int n = 0; n < BN; n++) { float d = norm_s[n * NC + c] - mu; var += d * d; }
    var *= (1.f / BN);
    float inv = 1.f / sqrtf(var + BN_EPS);
    #pragma unroll 8
    for (int n = 0; n < BN; n++) nbn_s[n * NC + c] = (norm_s[n * NC + c] - mu) * inv;
}

// ============================================================
// K3/K4: [64,512] @ W^T + bias, optional swish.  (R5 proven version)
// Warp-per-output-channel; W direct from gmem (16 independent LDGs);
// X staged transposed xs[k][12] so 8 n-values come from 2 LDS.128.
// ============================================================
__global__ void k_gemm(const float* __restrict__ W, const float* __restrict__ bias, int which) {
    const float* X = which ? h_s : nbn_s;
    float* Y       = which ? n1_s : h_s;
    __shared__ float xs[512][12];   // 24 KB, transposed
    int ng  = blockIdx.y * 8;
    int tid = threadIdx.x, warp = tid >> 5, lane = tid & 31;
    int o = blockIdx.x * 8 + warp;
    for (int i = tid; i < 8 * 512; i += 256) {
        int j = i >> 9, k = i & 511;
        xs[k][j] = X[(ng + j) * NC + k];
    }
    __syncthreads();
    const float* wrow = W + o * NC;
    float a0=0.f,a1=0.f,a2=0.f,a3=0.f,a4=0.f,a5=0.f,a6=0.f,a7=0.f;
    #pragma unroll
    for (int j = 0; j < 16; j++) {
        int k = lane + (j << 5);
        float w = wrow[k];
        float4 xa = *(const float4*)&xs[k][0];
        float4 xb = *(const float4*)&xs[k][4];
        a0 = fmaf(w, xa.x, a0);
        a1 = fmaf(w, xa.y, a1);
        a2 = fmaf(w, xa.z, a2);
        a3 = fmaf(w, xa.w, a3);
        a4 = fmaf(w, xb.x, a4);
        a5 = fmaf(w, xb.y, a5);
        a6 = fmaf(w, xb.z, a6);
        a7 = fmaf(w, xb.w, a7);
    }
    #pragma unroll
    for (int s = 16; s > 0; s >>= 1) {
        a0 += __shfl_xor_sync(0xffffffff, a0, s);
        a1 += __shfl_xor_sync(0xffffffff, a1, s);
        a2 += __shfl_xor_sync(0xffffffff, a2, s);
        a3 += __shfl_xor_sync(0xffffffff, a3, s);
        a4 += __shfl_xor_sync(0xffffffff, a4, s);
        a5 += __shfl_xor_sync(0xffffffff, a5, s);
        a6 += __shfl_xor_sync(0xffffffff, a6, s);
        a7 += __shfl_xor_sync(0xffffffff, a7, s);
    }
    if (lane == 0) {
        float b = bias[o];
        float v[8] = {a0+b, a1+b, a2+b, a3+b, a4+b, a5+b, a6+b, a7+b};
        #pragma unroll
        for (int j = 0; j < 8; j++) {
            float u = v[j];
            if (!which) u = u / (1.f + expf(-u));   // swish
            Y[(ng + j) * NC + o] = u;
        }
    }
}

// ============================================================
// K5: IELin fused with scalar_mul -> x1d_new (into d_out). (R5 version)
// ============================================================
__global__ void k_ielin(const float* __restrict__ Wie, float* __restrict__ x1dout) {
    __shared__ float gsT[128][12];  // 6 KB, transposed
    __shared__ int nrow[8], mrow[8];
    int rowbase = blockIdx.x * 8;
    int l, lbase;
    if (rowbase < 64)       { l = 0; lbase = 0; }
    else if (rowbase < 256) { l = 1; lbase = 64; }
    else if (rowbase < 576) { l = 2; lbase = 256; }
    else                    { l = 3; lbase = 576; }
    int nm = 2 * l + 1, off = REP_OFF_C[l];
    int tid = threadIdx.x, warp = tid >> 5, lane = tid & 31;
    if (tid < 8) {
        int rr = rowbase + tid - lbase;
        nrow[tid] = rr / nm;
        mrow[tid] = rr - nrow[tid] * nm;
    }
    __syncthreads();
    for (int idx = tid; idx < 8 * 128; idx += 256) {
        int j = idx >> 7, i = idx & 127;
        gsT[i][j] = g_s[nrow[j] * REP + off + mrow[j] * 128 + i];
    }
    __syncthreads();
    int o = blockIdx.y * 8 + warp;
    const float* wrow = Wie + (l * 128 + o) * 128;
    float a0=0.f,a1=0.f,a2=0.f,a3=0.f,a4=0.f,a5=0.f,a6=0.f,a7=0.f;
    #pragma unroll
    for (int j = 0; j < 4; j++) {
        int k = lane + (j << 5);
        float w = wrow[k];
        float4 ga = *(const float4*)&gsT[k][0];
        float4 gb = *(const float4*)&gsT[k][4];
        a0 = fmaf(w, ga.x, a0);
        a1 = fmaf(w, ga.y, a1);
        a2 = fmaf(w, ga.z, a2);
        a3 = fmaf(w, ga.w, a3);
        a4 = fmaf(w, gb.x, a4);
        a5 = fmaf(w, gb.y, a5);
        a6 = fmaf(w, gb.z, a6);
        a7 = fmaf(w, gb.w, a7);
    }
    #pragma unroll
    for (int s = 16; s > 0; s >>= 1) {
        a0 += __shfl_xor_sync(0xffffffff, a0, s);
        a1 += __shfl_xor_sync(0xffffffff, a1, s);
        a2 += __shfl_xor_sync(0xffffffff, a2, s);
        a3 += __shfl_xor_sync(0xffffffff, a3, s);
        a4 += __shfl_xor_sync(0xffffffff, a4, s);
        a5 += __shfl_xor_sync(0xffffffff, a5, s);
        a6 += __shfl_xor_sync(0xffffffff, a6, s);
        a7 += __shfl_xor_sync(0xffffffff, a7, s);
    }
    if (lane == 0) {
        float acc[8] = {a0, a1, a2, a3, a4, a5, a6, a7};
        #pragma unroll
        for (int j = 0; j < 8; j++) {
            int n = nrow[j];
            x1dout[n * REP + off + mrow[j] * 128 + o] =
                acc[j] * n1_s[n * NC + l * 128 + o];
        }
    }
}

// ============================================================
// K6 (fused, per-node, R5 structure): reduce + gate + gated apply.
// 8 blocks per node (512 total, all resident). Single per-node barrier.
// DELTA vs R5: phase-B output stores are STREAMING (__stcs, evict-
// first) so the 256 MB of writes don't evict phase-A x2d lines from
// L2 -> phase-B re-reads hit L2 more often.
// ============================================================
__global__ void __launch_bounds__(256, 4)
k_two(const float* __restrict__ x2d, const float* __restrict__ x1dnew,
      const float* __restrict__ Wg, const float* __restrict__ bg,
      const float* __restrict__ Wt, float* __restrict__ x2dout) {
    int n = blockIdx.x >> 3, seg = blockIdx.x & 7;
    int tid = threadIdx.x, warp = tid >> 5, lane = tid & 31;
    __shared__ float4 fs[512];      // 8 KB
    __shared__ float wacc[8][4];
    __shared__ float Msh[16];

    const float4* f4 = (const float4*)x1dnew + n * 512;
    for (int q = tid; q < 512; q += 256) fs[q] = f4[q];
    __syncthreads();

    // ---- phase A: reduce 64 rows (8 per warp) ----
    float ax = 0.f, ay = 0.f, az = 0.f, aw = 0.f;
    for (int r = 0; r < 8; r++) {
        int p = seg * 64 + warp * 8 + r;
        float4 fp = fs[p];
        const float4* row = (const float4*)x2d + ((size_t)n * 512 + p) * 512;
        #pragma unroll
        for (int j = 0; j < 16; j++) {
            int q = lane + (j << 5);
            float4 v  = row[q];
            float4 fq = fs[q];
            ax = fmaf(v.x * fq.x, fp.x, ax);
            ay = fmaf(v.y * fq.y, fp.y, ay);
            az = fmaf(v.z * fq.z, fp.z, az);
            aw = fmaf(v.w * fq.w, fp.w, aw);
        }
    }
    #pragma unroll
    for (int s = 16; s > 0; s >>= 1) {
        ax += __shfl_xor_sync(0xffffffff, ax, s);
        ay += __shfl_xor_sync(0xffffffff, ay, s);
        az += __shfl_xor_sync(0xffffffff, az, s);
        aw += __shfl_xor_sync(0xffffffff, aw, s);
    }
    if (lane == 0) { wacc[warp][0] = ax; wacc[warp][1] = ay; wacc[warp][2] = az; wacc[warp][3] = aw; }
    __syncthreads();
    if (tid < 4) {
        float s = 0.f;
        #pragma unroll
        for (int w = 0; w < 8; w++) s += wacc[w][tid];
        partN_s[n][seg][tid] = s;
        __threadfence();
    }
    __syncthreads();

    // ---- per-node barrier: 8 participants ----
    if (tid == 0) {
        atomicAdd(&barN_s[n], 1);
        while (*(volatile int*)&barN_s[n] < 8) __nanosleep(32);
    }
    __syncthreads();
    __threadfence();

    // ---- gate (redundant per block, deterministic fixed-order sum) ----
    if (tid == 0) {
        volatile float* pp = &partN_s[n][0][0];
        float a2[4] = {0.f, 0.f, 0.f, 0.f};
        #pragma unroll
        for (int s = 0; s < 8; s++)
            #pragma unroll
            for (int c = 0; c < 4; c++) a2[c] += pp[s * 4 + c];
        #pragma unroll
        for (int d = 0; d < 4; d++) {
            float pre = bg[d];
            #pragma unroll
            for (int c = 0; c < 4; c++) pre = fmaf(a2[c], Wg[d * 4 + c], pre);
            float gate = pre / (1.f + expf(-pre));
            #pragma unroll
            for (int c = 0; c < 4; c++) Msh[d * 4 + c] = gate * Wt[d * 4 + c];
        }
    }
    __syncthreads();

    // ---- phase B: gated 4x4 matvec over the same rows (L2-hot),
    //      streaming stores keep x2d resident in L2 ----
    float m[16];
    #pragma unroll
    for (int i = 0; i < 16; i++) m[i] = Msh[i];
    for (int r = 0; r < 8; r++) {
        int p = seg * 64 + warp * 8 + r;
        const float4* row  = (const float4*)x2d    + ((size_t)n * 512 + p) * 512;
        float4*       orow = (float4*)      x2dout + ((size_t)n * 512 + p) * 512;
        #pragma unroll
        for (int j = 0; j < 16; j++) {
            int q = lane + (j << 5);
            float4 v = row[q];
            float4 o;
            o.x = m[0]  * v.x + m[1]  * v.y + m[2]  * v.z + m[3]  * v.w;
            o.y = m[4]  * v.x + m[5]  * v.y + m[6]  * v.z + m[7]  * v.w;
            o.z = m[8]  * v.x + m[9]  * v.y + m[10] * v.z + m[11] * v.w;
            o.w = m[12] * v.x + m[13] * v.y + m[14] * v.z + m[15] * v.w;
            __stcs(&orow[q], o);   // evict-first: don't pollute L2
        }
    }
}

// ============================================================
extern "C" void kernel_launch(void* const* d_in, const int* in_sizes, int n_in,
                              void* d_out, int out_size) {
    const float* x1d = (const float*)d_in[0];
    const float* x2d = (const float*)d_in[1];
    const float* W1  = (const float*)d_in[2];
    const float* b1  = (const float*)d_in[3];
    const float* W2  = (const float*)d_in[4];
    const float* b2  = (const float*)d_in[5];
    const float* Wie = (const float*)d_in[6];
    const float* Wt  = (const float*)d_in[7];
    const float* Wg  = (const float*)d_in[8];
    const float* bg  = (const float*)d_in[9];
    float* out = (float*)d_out;
    float* x1dnew = out;                       // [64, 2048]
    float* x2dnew = out + (size_t)BN * REP;    // [64, 512, 512, 4]

    k_init<<<1, 64>>>();
    k_norm_gauge<<<BN, 256>>>(x1d);
    k_bn<<<4, 128>>>();
    k_gemm<<<dim3(64, 8), 256>>>(W1, b1, 0);   // swish
    k_gemm<<<dim3(64, 8), 256>>>(W2, b2, 1);   // linear
    k_ielin<<<dim3(128, 16), 256>>>(Wie, x1dnew);
    k_two<<<512, 256>>>(x2d, x1dnew, Wg, bg, Wt, x2dnew);
}

// round 9
// speedup vs baseline: 1.1970x; 1.0123x over previous
#include <cuda_runtime.h>
#include <math.h>

// ---- static problem dims ----
#define BN      64      // batch (nodes)
#define NCL     128
#define NC      512     // total channels
#define REP     2048    // rep components
#define DD      512     // folded dim
#define NORM_EPS 1e-2f
#define BN_EPS   1e-5f

__device__ __constant__ int REP_OFF_C[4] = {0, 128, 512, 1152};

// ---- scratch (__device__ globals: allocation-free) ----
__device__ float g_s[BN * REP];      // gauge tensor
__device__ float norm_s[BN * NC];    // per-(l,channel) norms
__device__ float nbn_s[BN * NC];     // batchnormed norms
__device__ float h_s[BN * NC];       // MLP hidden
__device__ float n1_s[BN * NC];      // MLP out
__device__ float partN_s[BN][8][4];  // per-node per-segment bilinear partials
__device__ float M2_s[BN][16];       // per-n gated 4x4: M[d][c]=gate[n,d]*Wt[d,c]

// ============================================================
// K1: per-node norms + gauge tensor.  One block per n.
// ============================================================
__global__ void k_norm_gauge(const float* __restrict__ x1d) {
    int n = blockIdx.x;
    __shared__ float xs[REP];   // 8 KB
    __shared__ float ns[NC];    // 2 KB
    const float* xr = x1d + n * REP;
    for (int i = threadIdx.x; i < REP; i += 256) xs[i] = xr[i];
    __syncthreads();
    for (int c = threadIdx.x; c < NC; c += 256) {
        int l = c >> 7, j = c & 127, off = REP_OFF_C[l], nm = 2 * l + 1;
        float s = 0.f;
        #pragma unroll 7
        for (int m = 0; m < nm; m++) { float v = xs[off + m * 128 + j]; s += v * v; }
        float nv = sqrtf(s);
        ns[c] = nv;
        norm_s[n * NC + c] = nv;
    }
    __syncthreads();
    for (int r = threadIdx.x; r < REP; r += 256) {
        int l = (r < 128) ? 0 : (r < 512) ? 1 : (r < 1152) ? 2 : 3;
        int c = l * 128 + ((r - REP_OFF_C[l]) & 127);
        g_s[n * REP + r] = xs[r] / (ns[c] + NORM_EPS);
    }
}

// ============================================================
// K2: batchnorm over batch axis. grid 4 x 128 threads.
// ============================================================
__global__ void k_bn() {
    int c = blockIdx.x * 128 + threadIdx.x;
    float mu = 0.f;
    #pragma unroll 8
    for (int n = 0; n < BN; n++) mu += norm_s[n * NC + c];
    mu *= (1.f / BN);
    float var = 0.f;
    #pragma unroll 8
    for (int n = 0; n < BN; n++) { float d = norm_s[n * NC + c] - mu; var += d * d; }
    var *= (1.f / BN);
    float inv = 1.f / sqrtf(var + BN_EPS);
    #pragma unroll 8
    for (int n = 0; n < BN; n++) nbn_s[n * NC + c] = (norm_s[n * NC + c] - mu) * inv;
}

// ============================================================
// K3/K4: [64,512] @ W^T + bias, optional swish.  (proven R5 version)
// ============================================================
__global__ void k_gemm(const float* __restrict__ W, const float* __restrict__ bias, int which) {
    const float* X = which ? h_s : nbn_s;
    float* Y       = which ? n1_s : h_s;
    __shared__ float xs[512][12];   // 24 KB, transposed
    int ng  = blockIdx.y * 8;
    int tid = threadIdx.x, warp = tid >> 5, lane = tid & 31;
    int o = blockIdx.x * 8 + warp;
    for (int i = tid; i < 8 * 512; i += 256) {
        int j = i >> 9, k = i & 511;
        xs[k][j] = X[(ng + j) * NC + k];
    }
    __syncthreads();
    const float* wrow = W + o * NC;
    float a0=0.f,a1=0.f,a2=0.f,a3=0.f,a4=0.f,a5=0.f,a6=0.f,a7=0.f;
    #pragma unroll
    for (int j = 0; j < 16; j++) {
        int k = lane + (j << 5);
        float w = wrow[k];
        float4 xa = *(const float4*)&xs[k][0];
        float4 xb = *(const float4*)&xs[k][4];
        a0 = fmaf(w, xa.x, a0);
        a1 = fmaf(w, xa.y, a1);
        a2 = fmaf(w, xa.z, a2);
        a3 = fmaf(w, xa.w, a3);
        a4 = fmaf(w, xb.x, a4);
        a5 = fmaf(w, xb.y, a5);
        a6 = fmaf(w, xb.z, a6);
        a7 = fmaf(w, xb.w, a7);
    }
    #pragma unroll
    for (int s = 16; s > 0; s >>= 1) {
        a0 += __shfl_xor_sync(0xffffffff, a0, s);
        a1 += __shfl_xor_sync(0xffffffff, a1, s);
        a2 += __shfl_xor_sync(0xffffffff, a2, s);
        a3 += __shfl_xor_sync(0xffffffff, a3, s);
        a4 += __shfl_xor_sync(0xffffffff, a4, s);
        a5 += __shfl_xor_sync(0xffffffff, a5, s);
        a6 += __shfl_xor_sync(0xffffffff, a6, s);
        a7 += __shfl_xor_sync(0xffffffff, a7, s);
    }
    if (lane == 0) {
        float b = bias[o];
        float v[8] = {a0+b, a1+b, a2+b, a3+b, a4+b, a5+b, a6+b, a7+b};
        #pragma unroll
        for (int j = 0; j < 8; j++) {
            float u = v[j];
            if (!which) u = u / (1.f + expf(-u));   // swish
            Y[(ng + j) * NC + o] = u;
        }
    }
}

// ============================================================
// K5: IELin fused with scalar_mul -> x1d_new (into d_out). (R5 version)
// ============================================================
__global__ void k_ielin(const float* __restrict__ Wie, float* __restrict__ x1dout) {
    __shared__ float gsT[128][12];  // 6 KB, transposed
    __shared__ int nrow[8], mrow[8];
    int rowbase = blockIdx.x * 8;
    int l, lbase;
    if (rowbase < 64)       { l = 0; lbase = 0; }
    else if (rowbase < 256) { l = 1; lbase = 64; }
    else if (rowbase < 576) { l = 2; lbase = 256; }
    else                    { l = 3; lbase = 576; }
    int nm = 2 * l + 1, off = REP_OFF_C[l];
    int tid = threadIdx.x, warp = tid >> 5, lane = tid & 31;
    if (tid < 8) {
        int rr = rowbase + tid - lbase;
        nrow[tid] = rr / nm;
        mrow[tid] = rr - nrow[tid] * nm;
    }
    __syncthreads();
    for (int idx = tid; idx < 8 * 128; idx += 256) {
        int j = idx >> 7, i = idx & 127;
        gsT[i][j] = g_s[nrow[j] * REP + off + mrow[j] * 128 + i];
    }
    __syncthreads();
    int o = blockIdx.y * 8 + warp;
    const float* wrow = Wie + (l * 128 + o) * 128;
    float a0=0.f,a1=0.f,a2=0.f,a3=0.f,a4=0.f,a5=0.f,a6=0.f,a7=0.f;
    #pragma unroll
    for (int j = 0; j < 4; j++) {
        int k = lane + (j << 5);
        float w = wrow[k];
        float4 ga = *(const float4*)&gsT[k][0];
        float4 gb = *(const float4*)&gsT[k][4];
        a0 = fmaf(w, ga.x, a0);
        a1 = fmaf(w, ga.y, a1);
        a2 = fmaf(w, ga.z, a2);
        a3 = fmaf(w, ga.w, a3);
        a4 = fmaf(w, gb.x, a4);
        a5 = fmaf(w, gb.y, a5);
        a6 = fmaf(w, gb.z, a6);
        a7 = fmaf(w, gb.w, a7);
    }
    #pragma unroll
    for (int s = 16; s > 0; s >>= 1) {
        a0 += __shfl_xor_sync(0xffffffff, a0, s);
        a1 += __shfl_xor_sync(0xffffffff, a1, s);
        a2 += __shfl_xor_sync(0xffffffff, a2, s);
        a3 += __shfl_xor_sync(0xffffffff, a3, s);
        a4 += __shfl_xor_sync(0xffffffff, a4, s);
        a5 += __shfl_xor_sync(0xffffffff, a5, s);
        a6 += __shfl_xor_sync(0xffffffff, a6, s);
        a7 += __shfl_xor_sync(0xffffffff, a7, s);
    }
    if (lane == 0) {
        float acc[8] = {a0, a1, a2, a3, a4, a5, a6, a7};
        #pragma unroll
        for (int j = 0; j < 8; j++) {
            int n = nrow[j];
            x1dout[n * REP + off + mrow[j] * 128 + o] =
                acc[j] * n1_s[n * NC + l * 128 + o];
        }
    }
}

// ============================================================
// K6: bilinear reduction (phase A only, no barriers).
// Block (n = bid>>3, seg = bid&7) reduces rows seg*64..+64 of node n
// (warp w owns rows warp*8+r, r ascending) -> partN_s[n][seg][0..3].
// The LAST rows read (high r) are what lingers in L2 for k_pass2.
// ============================================================
__global__ void __launch_bounds__(256, 4)
k_reduce(const float* __restrict__ x2d, const float* __restrict__ x1dnew) {
    int n = blockIdx.x >> 3, seg = blockIdx.x & 7;
    int tid = threadIdx.x, warp = tid >> 5, lane = tid & 31;
    __shared__ float4 fs[512];      // 8 KB
    __shared__ float wacc[8][4];
    const float4* f4 = (const float4*)x1dnew + n * 512;
    for (int q = tid; q < 512; q += 256) fs[q] = f4[q];
    __syncthreads();
    float ax = 0.f, ay = 0.f, az = 0.f, aw = 0.f;
    for (int r = 0; r < 8; r++) {
        int p = seg * 64 + warp * 8 + r;
        float4 fp = fs[p];
        const float4* row = (const float4*)x2d + ((size_t)n * 512 + p) * 512;
        #pragma unroll
        for (int j = 0; j < 16; j++) {
            int q = lane + (j << 5);
            float4 v  = row[q];
            float4 fq = fs[q];
            ax = fmaf(v.x * fq.x, fp.x, ax);
            ay = fmaf(v.y * fq.y, fp.y, ay);
            az = fmaf(v.z * fq.z, fp.z, az);
            aw = fmaf(v.w * fq.w, fp.w, aw);
        }
    }
    #pragma unroll
    for (int s = 16; s > 0; s >>= 1) {
        ax += __shfl_xor_sync(0xffffffff, ax, s);
        ay += __shfl_xor_sync(0xffffffff, ay, s);
        az += __shfl_xor_sync(0xffffffff, az, s);
        aw += __shfl_xor_sync(0xffffffff, aw, s);
    }
    if (lane == 0) { wacc[warp][0] = ax; wacc[warp][1] = ay; wacc[warp][2] = az; wacc[warp][3] = aw; }
    __syncthreads();
    if (tid < 4) {
        float s = 0.f;
        #pragma unroll
        for (int w = 0; w < 8; w++) s += wacc[w][tid];
        partN_s[n][seg][tid] = s;
    }
}

// ============================================================
// K7: gate = swish(a2 @ Wg^T + bg) folded into per-n 4x4 M.
// One block, 64 threads (one per node). Deterministic fixed-order sum.
// ============================================================
__global__ void k_gate(const float* __restrict__ Wg, const float* __restrict__ bg,
                       const float* __restrict__ Wt) {
    int n = threadIdx.x;
    if (n >= BN) return;
    float a2[4] = {0.f, 0.f, 0.f, 0.f};
    #pragma unroll
    for (int s = 0; s < 8; s++)
        #pragma unroll
        for (int c = 0; c < 4; c++) a2[c] += partN_s[n][s][c];
    #pragma unroll
    for (int d = 0; d < 4; d++) {
        float pre = bg[d];
        #pragma unroll
        for (int c = 0; c < 4; c++) pre = fmaf(a2[c], Wg[d * 4 + c], pre);
        float gate = pre / (1.f + expf(-pre));
        #pragma unroll
        for (int c = 0; c < 4; c++) M2_s[n][d * 4 + c] = gate * Wt[d * 4 + c];
    }
}

// ============================================================
// K8: gated 4x4 matvec, SAME (n,seg,warp)->rows mapping as k_reduce
// but iterating r in REVERSE: the first rows read are exactly the
// lines k_reduce read last -> L2 tail hits. Streaming stores keep
// those reads resident.
// ============================================================
__global__ void __launch_bounds__(256, 4)
k_pass2(const float* __restrict__ x2d, float* __restrict__ x2dout) {
    int n = blockIdx.x >> 3, seg = blockIdx.x & 7;
    int tid = threadIdx.x, warp = tid >> 5, lane = tid & 31;
    float m[16];
    #pragma unroll
    for (int i = 0; i < 16; i++) m[i] = M2_s[n][i];
    for (int r = 7; r >= 0; r--) {
        int p = seg * 64 + warp * 8 + r;
        const float4* row  = (const float4*)x2d    + ((size_t)n * 512 + p) * 512;
        float4*       orow = (float4*)      x2dout + ((size_t)n * 512 + p) * 512;
        #pragma unroll
        for (int j = 0; j < 16; j++) {
            int q = lane + (j << 5);
            float4 v = row[q];
            float4 o;
            o.x = m[0]  * v.x + m[1]  * v.y + m[2]  * v.z + m[3]  * v.w;
            o.y = m[4]  * v.x + m[5]  * v.y + m[6]  * v.z + m[7]  * v.w;
            o.z = m[8]  * v.x + m[9]  * v.y + m[10] * v.z + m[11] * v.w;
            o.w = m[12] * v.x + m[13] * v.y + m[14] * v.z + m[15] * v.w;
            __stcs(&orow[q], o);   // evict-first: protect read lines in L2
        }
    }
}

// ============================================================
extern "C" void kernel_launch(void* const* d_in, const int* in_sizes, int n_in,
                              void* d_out, int out_size) {
    const float* x1d = (const float*)d_in[0];
    const float* x2d = (const float*)d_in[1];
    const float* W1  = (const float*)d_in[2];
    const float* b1  = (const float*)d_in[3];
    const float* W2  = (const float*)d_in[4];
    const float* b2  = (const float*)d_in[5];
    const float* Wie = (const float*)d_in[6];
    const float* Wt  = (const float*)d_in[7];
    const float* Wg  = (const float*)d_in[8];
    const float* bg  = (const float*)d_in[9];
    float* out = (float*)d_out;
    float* x1dnew = out;                       // [64, 2048]
    float* x2dnew = out + (size_t)BN * REP;    // [64, 512, 512, 4]

    k_norm_gauge<<<BN, 256>>>(x1d);
    k_bn<<<4, 128>>>();
    k_gemm<<<dim3(64, 8), 256>>>(W1, b1, 0);   // swish
    k_gemm<<<dim3(64, 8), 256>>>(W2, b2, 1);   // linear
    k_ielin<<<dim3(128, 16), 256>>>(Wie, x1dnew);
    k_reduce<<<512, 256>>>(x2d, x1dnew);
    k_gate<<<1, 64>>>(Wg, bg, Wt);
    k_pass2<<<512, 256>>>(x2d, x2dnew);
}